// round 7
// baseline (speedup 1.0000x reference)
#include <cuda_runtime.h>
#include <cuda_bf16.h>

// TargetedDropout inference path:
//   per channel c (last axis, C=1024), threshold = 16383-th smallest |x| over
//   the N=32768 leading entries; out = (|x| <= thr[c]) ? 0 : x.
//
// Strategy: statistical-window candidate collection (|x| in [0.64,0.71],
// 8-sigma safe for N(0,1) sample median) + exact in-window selection, with an
// always-correct byte-wise radix-select fallback per column.

#define C_DIM   1024
#define N_ROWS  32768
#define RANK0   16383          // int(0.5 * 32768) - 1
#define W_LO    0.64f
#define W_HI    0.71f
#define CAP     2048           // per-column candidate capacity (mean 1457, sd 37)
#define SMALLC  288            // bin-mate capacity in select

__device__ int       g_cnt_below[C_DIM];
__device__ int       g_cand_cnt[C_DIM];
__device__ unsigned  g_cand[CAP * C_DIM];          // layout [pos][col], 8 MB .bss
__device__ __align__(16) float g_thr[C_DIM];

// -------------------------------------------------------------------------
// Pass 0: zero the per-call counters (graph replays must be deterministic)
// -------------------------------------------------------------------------
__global__ void k_zero() {
    int i = threadIdx.x;
    if (i < C_DIM) { g_cnt_below[i] = 0; g_cand_cnt[i] = 0; }
}

// -------------------------------------------------------------------------
// Pass 1: one full read of x. Thread t always owns columns 4t..4t+3 (a float4
// row chunk), so below-counts accumulate in registers. In-window values are
// appended to global candidate scratch.
// grid = 1024 blocks x 256 threads; each block covers 32 rows.
// -------------------------------------------------------------------------
__global__ void __launch_bounds__(256) k_collect(const float4* __restrict__ x) {
    const int t    = threadIdx.x;
    const int col0 = t * 4;
    const int row0 = blockIdx.x * 32;

    int c0 = 0, c1 = 0, c2 = 0, c3 = 0;

    for (int j = 0; j < 32; ++j) {
        float4 v = x[(row0 + j) * 256 + t];
        float a;

        a = fabsf(v.x);
        if (a < W_LO) c0++;
        else if (a <= W_HI) {
            int p = atomicAdd(&g_cand_cnt[col0 + 0], 1);
            if (p < CAP) g_cand[p * C_DIM + col0 + 0] = __float_as_uint(a);
        }
        a = fabsf(v.y);
        if (a < W_LO) c1++;
        else if (a <= W_HI) {
            int p = atomicAdd(&g_cand_cnt[col0 + 1], 1);
            if (p < CAP) g_cand[p * C_DIM + col0 + 1] = __float_as_uint(a);
        }
        a = fabsf(v.z);
        if (a < W_LO) c2++;
        else if (a <= W_HI) {
            int p = atomicAdd(&g_cand_cnt[col0 + 2], 1);
            if (p < CAP) g_cand[p * C_DIM + col0 + 2] = __float_as_uint(a);
        }
        a = fabsf(v.w);
        if (a < W_LO) c3++;
        else if (a <= W_HI) {
            int p = atomicAdd(&g_cand_cnt[col0 + 3], 1);
            if (p < CAP) g_cand[p * C_DIM + col0 + 3] = __float_as_uint(a);
        }
    }

    if (c0) atomicAdd(&g_cnt_below[col0 + 0], c0);
    if (c1) atomicAdd(&g_cnt_below[col0 + 1], c1);
    if (c2) atomicAdd(&g_cnt_below[col0 + 2], c2);
    if (c3) atomicAdd(&g_cnt_below[col0 + 3], c3);
}

// -------------------------------------------------------------------------
// Pass 2: one block per column. Main path: all candidates share exponent 126
// (window subset of [0.5,1)), so a 4096-bin histogram on mantissa bits [22:11]
// plus an exact resolve among bin-mates yields the exact k-th |x| value.
// Fallback (rank outside window / any cap overflow): exact 4-pass byte-wise
// MSD radix select over the raw column from global memory.
// -------------------------------------------------------------------------
__global__ void __launch_bounds__(256) k_select(const float* __restrict__ x) {
    __shared__ unsigned sdata[CAP];     //  8 KB
    __shared__ int      hist[4096];     // 16 KB (fallback reuses first 256)
    __shared__ int      seg[256];
    __shared__ unsigned ssmall[SMALLC];
    __shared__ int      s_smallcnt;
    __shared__ int      s_fb;
    __shared__ int      s_bin, s_r2;
    __shared__ unsigned s_prefix;
    __shared__ int      s_rank;

    const int c = blockIdx.x;
    const int t = threadIdx.x;

    const int n     = g_cand_cnt[c];
    const int below = g_cnt_below[c];
    const int r     = RANK0 - below;

    if (t == 0) {
        s_fb = (n > CAP || r < 0 || r >= n) ? 1 : 0;
        s_smallcnt = 0;
    }
    __syncthreads();

    if (!s_fb) {
        for (int i = t; i < n; i += 256) sdata[i] = g_cand[i * C_DIM + c];
        for (int i = t; i < 4096; i += 256) hist[i] = 0;
        __syncthreads();

        for (int i = t; i < n; i += 256)
            atomicAdd(&hist[(sdata[i] >> 11) & 0xFFF], 1);
        __syncthreads();

        // segmented prefix scan: 256 segments of 16 bins
        int s = 0;
        #pragma unroll
        for (int u = 0; u < 16; ++u) s += hist[t * 16 + u];
        seg[t] = s;
        __syncthreads();

        if (t == 0) {
            int cum = 0, si = 0;
            while (cum + seg[si] <= r) { cum += seg[si]; ++si; }
            int b = si * 16;
            while (cum + hist[b] <= r) { cum += hist[b]; ++b; }
            s_bin = b;
            s_r2  = r - cum;
        }
        __syncthreads();

        const unsigned bsel = (unsigned)s_bin;
        for (int i = t; i < n; i += 256) {
            if (((sdata[i] >> 11) & 0xFFF) == bsel) {
                int p = atomicAdd(&s_smallcnt, 1);
                if (p < SMALLC) ssmall[p] = sdata[i];
            }
        }
        __syncthreads();

        if (t == 0) {
            int m = s_smallcnt;
            if (m > SMALLC) {
                s_fb = 1;                      // pathological: redo exactly
            } else {
                const int r2 = s_r2;
                unsigned ans = 0;
                for (int i = 0; i < m; ++i) {
                    unsigned v = ssmall[i];
                    int less = 0, eq = 0;
                    for (int j = 0; j < m; ++j) {
                        less += (ssmall[j] < v);
                        eq   += (ssmall[j] == v);
                    }
                    if (less <= r2 && r2 < less + eq) { ans = v; break; }
                }
                g_thr[c] = __uint_as_float(ans);
            }
        }
        __syncthreads();
    }

    if (s_fb) {
        // Exact MSD radix select over the whole column (4 x 8-bit passes).
        if (t == 0) { s_prefix = 0; s_rank = RANK0; }
        for (int shift = 24; shift >= 0; shift -= 8) {
            hist[t] = 0;                       // only 256 bins used here
            __syncthreads();
            const unsigned pfx = s_prefix;
            const int hs = shift + 8;
            for (int row = t; row < N_ROWS; row += 256) {
                unsigned key = __float_as_uint(fabsf(x[row * C_DIM + c]));
                bool ok = (hs >= 32) || ((key >> hs) == (pfx >> hs));
                if (ok) atomicAdd(&hist[(key >> shift) & 255], 1);
            }
            __syncthreads();
            if (t == 0) {
                int cum = 0, b = 0;
                while (cum + hist[b] <= s_rank) { cum += hist[b]; ++b; }
                s_rank  -= cum;
                s_prefix |= ((unsigned)b) << shift;
            }
            __syncthreads();
        }
        if (t == 0) g_thr[c] = __uint_as_float(s_prefix);
    }
}

// -------------------------------------------------------------------------
// Pass 3: streaming mask. blockDim must be 256 so each thread's column group
// (threadIdx.x) is loop-invariant -> threshold float4 hoisted out of the loop.
// -------------------------------------------------------------------------
__global__ void __launch_bounds__(256) k_mask(const float4* __restrict__ x,
                                              float4* __restrict__ out,
                                              int n4) {
    const float4 thr = reinterpret_cast<const float4*>(g_thr)[threadIdx.x];
    const int stride = gridDim.x * blockDim.x;   // multiple of 256
    for (int i = blockIdx.x * blockDim.x + threadIdx.x; i < n4; i += stride) {
        float4 v = x[i];
        float4 o;
        o.x = (fabsf(v.x) <= thr.x) ? 0.0f : v.x;
        o.y = (fabsf(v.y) <= thr.y) ? 0.0f : v.y;
        o.z = (fabsf(v.z) <= thr.z) ? 0.0f : v.z;
        o.w = (fabsf(v.w) <= thr.w) ? 0.0f : v.w;
        out[i] = o;
    }
}

extern "C" void kernel_launch(void* const* d_in, const int* in_sizes, int n_in,
                              void* d_out, int out_size) {
    const float* x  = (const float*)d_in[0];
    float* out      = (float*)d_out;
    const int n4    = out_size / 4;              // 8,388,608 float4s

    k_zero   <<<1, 1024>>>();
    k_collect<<<1024, 256>>>((const float4*)x);
    k_select <<<1024, 256>>>(x);
    k_mask   <<<4096, 256>>>((const float4*)x, (float4*)out, n4);
}

// round 8
// speedup vs baseline: 1.6569x; 1.6569x over previous
#include <cuda_runtime.h>
#include <cuda_bf16.h>

// TargetedDropout inference path:
//   per channel c (last axis, C=1024), threshold = 16383-th smallest |x| over
//   the N=32768 leading entries; out = (|x| <= thr[c]) ? 0 : x.
//
// Round 7 redesign: ZERO global atomics. Deterministic per-(column,block)
// candidate slots + non-atomic count arrays; exact in-window histogram select;
// always-correct per-column radix-select fallback for statistical outliers.

#define C_DIM   1024
#define N_ROWS  32768
#define RANK0   16383          // int(0.5 * 32768) - 1
#define W_LO    0.64f
#define W_HI    0.71f
#define NBLK    256            // collect blocks
#define RPB     (N_ROWS / NBLK)// 128 rows per collect block
#define CAPB    24             // per column-block candidate cap (lambda = 5.69)
#define CAP     2048           // per-column total candidate cap (mean 1457, sd 37)
#define SMALLC  288            // bin-mate capacity in select

// [col][blk][CAPB] : per-column contiguous -> coalesced select reads. 24 MB.
__device__ unsigned g_cand[(size_t)C_DIM * NBLK * CAPB];
// [blk][col] : warp-coalesced collect writes. 1 MB each.
__device__ int      g_cnt[NBLK * C_DIM];
__device__ int      g_below[NBLK * C_DIM];
__device__ __align__(16) float g_thr[C_DIM];

// -------------------------------------------------------------------------
// Pass 1: one full read of x. Thread t exclusively owns columns 4t..4t+3
// within its block -> counts and candidate slots need no synchronization.
// grid = 256 blocks x 256 threads; each block covers 128 rows.
// -------------------------------------------------------------------------
__global__ void __launch_bounds__(256) k_collect(const float4* __restrict__ x) {
    const int t    = threadIdx.x;
    const int blk  = blockIdx.x;
    const int col0 = t * 4;
    const int row0 = blk * RPB;

    int b0 = 0, b1 = 0, b2 = 0, b3 = 0;   // below-window counts
    int n0 = 0, n1 = 0, n2 = 0, n3 = 0;   // in-window candidate counts

    unsigned* c0 = &g_cand[(size_t)(col0 + 0) * (NBLK * CAPB) + blk * CAPB];
    unsigned* c1 = c0 + (size_t)(NBLK * CAPB);
    unsigned* c2 = c1 + (size_t)(NBLK * CAPB);
    unsigned* c3 = c2 + (size_t)(NBLK * CAPB);

    #pragma unroll 4
    for (int j = 0; j < RPB; ++j) {
        float4 v = x[(size_t)(row0 + j) * 256 + t];
        float a;

        a = fabsf(v.x);
        if (a < W_LO) b0++;
        else if (a <= W_HI) { if (n0 < CAPB) c0[n0] = __float_as_uint(a); n0++; }

        a = fabsf(v.y);
        if (a < W_LO) b1++;
        else if (a <= W_HI) { if (n1 < CAPB) c1[n1] = __float_as_uint(a); n1++; }

        a = fabsf(v.z);
        if (a < W_LO) b2++;
        else if (a <= W_HI) { if (n2 < CAPB) c2[n2] = __float_as_uint(a); n2++; }

        a = fabsf(v.w);
        if (a < W_LO) b3++;
        else if (a <= W_HI) { if (n3 < CAPB) c3[n3] = __float_as_uint(a); n3++; }
    }

    const int base = blk * C_DIM + col0;   // [blk][col]: coalesced stores
    g_cnt[base + 0] = n0;  g_cnt[base + 1] = n1;
    g_cnt[base + 2] = n2;  g_cnt[base + 3] = n3;
    g_below[base + 0] = b0;  g_below[base + 1] = b1;
    g_below[base + 2] = b2;  g_below[base + 3] = b3;
}

// -------------------------------------------------------------------------
// Pass 2: one block per column. Sum the 256 per-block counts, compact the
// candidates into shared, then exact selection: all candidates share exponent
// 126 (window subset of [0.5,1)), so a 4096-bin histogram on mantissa bits
// [22:11] plus an exact resolve among bin-mates yields the exact k-th |x|.
// Fallback (rank outside window / any cap overflow): exact 4-pass byte-wise
// MSD radix select over the raw column.
// -------------------------------------------------------------------------
__global__ void __launch_bounds__(256) k_select(const float* __restrict__ x) {
    __shared__ unsigned sdata[CAP];     //  8 KB
    __shared__ int      hist[4096];     // 16 KB (also below-scratch, fallback bins)
    __shared__ int      seg[256];       // count scratch, then scan segments
    __shared__ int      offs[NBLK];
    __shared__ unsigned ssmall[SMALLC];
    __shared__ int      s_smallcnt;
    __shared__ int      s_fb, s_n, s_r;
    __shared__ int      s_bin, s_r2;
    __shared__ unsigned s_prefix;
    __shared__ int      s_rank;

    const int c = blockIdx.x;
    const int t = threadIdx.x;          // == blk index (NBLK == 256)

    const int cntb = g_cnt[t * C_DIM + c];
    const int belb = g_below[t * C_DIM + c];
    seg[t]  = cntb;
    hist[t] = belb;
    __syncthreads();

    if (t == 0) {
        int tot = 0, mx = 0, bel = 0;
        for (int i = 0; i < NBLK; ++i) {
            offs[i] = tot;
            tot += seg[i];
            if (seg[i] > mx) mx = seg[i];
            bel += hist[i];
        }
        const int r = RANK0 - bel;
        s_n  = tot;
        s_r  = r;
        s_fb = (mx > CAPB || tot > CAP || r < 0 || r >= tot) ? 1 : 0;
        s_smallcnt = 0;
    }
    __syncthreads();

    const int n = s_n;
    const int r = s_r;

    if (!s_fb) {
        // Compact: thread t copies its block-segment (<= CAPB entries, L2 hits).
        {
            const unsigned* src = &g_cand[(size_t)c * (NBLK * CAPB) + t * CAPB];
            const int o = offs[t];
            for (int j = 0; j < cntb; ++j) sdata[o + j] = src[j];
        }
        for (int i = t; i < 4096; i += 256) hist[i] = 0;
        __syncthreads();

        for (int i = t; i < n; i += 256)
            atomicAdd(&hist[(sdata[i] >> 11) & 0xFFF], 1);
        __syncthreads();

        // segmented prefix: 256 segments of 16 bins
        int s = 0;
        #pragma unroll
        for (int u = 0; u < 16; ++u) s += hist[t * 16 + u];
        seg[t] = s;
        __syncthreads();

        if (t == 0) {
            int cum = 0, si = 0;
            while (cum + seg[si] <= r) { cum += seg[si]; ++si; }
            int b = si * 16;
            while (cum + hist[b] <= r) { cum += hist[b]; ++b; }
            s_bin = b;
            s_r2  = r - cum;
        }
        __syncthreads();

        const unsigned bsel = (unsigned)s_bin;
        for (int i = t; i < n; i += 256) {
            if (((sdata[i] >> 11) & 0xFFF) == bsel) {
                int p = atomicAdd(&s_smallcnt, 1);
                if (p < SMALLC) ssmall[p] = sdata[i];
            }
        }
        __syncthreads();

        if (t == 0) {
            int m = s_smallcnt;
            if (m > SMALLC) {
                s_fb = 1;                      // pathological: redo exactly
            } else {
                const int r2 = s_r2;
                unsigned ans = 0;
                for (int i = 0; i < m; ++i) {
                    unsigned v = ssmall[i];
                    int less = 0, eq = 0;
                    for (int j = 0; j < m; ++j) {
                        less += (ssmall[j] < v);
                        eq   += (ssmall[j] == v);
                    }
                    if (less <= r2 && r2 < less + eq) { ans = v; break; }
                }
                g_thr[c] = __uint_as_float(ans);
            }
        }
        __syncthreads();
    }

    if (s_fb) {
        // Exact MSD radix select over the whole column (4 x 8-bit passes).
        if (t == 0) { s_prefix = 0; s_rank = RANK0; }
        for (int shift = 24; shift >= 0; shift -= 8) {
            hist[t] = 0;                       // only 256 bins used here
            __syncthreads();
            const unsigned pfx = s_prefix;
            const int hs = shift + 8;
            for (int row = t; row < N_ROWS; row += 256) {
                unsigned key = __float_as_uint(fabsf(x[(size_t)row * C_DIM + c]));
                bool ok = (hs >= 32) || ((key >> hs) == (pfx >> hs));
                if (ok) atomicAdd(&hist[(key >> shift) & 255], 1);
            }
            __syncthreads();
            if (t == 0) {
                int cum = 0, b = 0;
                while (cum + hist[b] <= s_rank) { cum += hist[b]; ++b; }
                s_rank  -= cum;
                s_prefix |= ((unsigned)b) << shift;
            }
            __syncthreads();
        }
        if (t == 0) g_thr[c] = __uint_as_float(s_prefix);
    }
}

// -------------------------------------------------------------------------
// Pass 3: streaming mask. blockDim must be 256 so each thread's column group
// (threadIdx.x) is loop-invariant -> threshold float4 hoisted out of the loop.
// -------------------------------------------------------------------------
__global__ void __launch_bounds__(256) k_mask(const float4* __restrict__ x,
                                              float4* __restrict__ out,
                                              int n4) {
    const float4 thr = reinterpret_cast<const float4*>(g_thr)[threadIdx.x];
    const int stride = gridDim.x * blockDim.x;   // multiple of 256
    for (int i = blockIdx.x * blockDim.x + threadIdx.x; i < n4; i += stride) {
        float4 v = x[i];
        float4 o;
        o.x = (fabsf(v.x) <= thr.x) ? 0.0f : v.x;
        o.y = (fabsf(v.y) <= thr.y) ? 0.0f : v.y;
        o.z = (fabsf(v.z) <= thr.z) ? 0.0f : v.z;
        o.w = (fabsf(v.w) <= thr.w) ? 0.0f : v.w;
        out[i] = o;
    }
}

extern "C" void kernel_launch(void* const* d_in, const int* in_sizes, int n_in,
                              void* d_out, int out_size) {
    const float* x = (const float*)d_in[0];
    float* out     = (float*)d_out;
    const int n4   = out_size / 4;               // 8,388,608 float4s

    k_collect<<<NBLK, 256>>>((const float4*)x);
    k_select <<<C_DIM, 256>>>(x);
    k_mask   <<<8192, 256>>>((const float4*)x, (float4*)out, n4);
}

// round 9
// speedup vs baseline: 1.8533x; 1.1185x over previous
#include <cuda_runtime.h>
#include <cuda_bf16.h>

// TargetedDropout inference path:
//   per channel c (last axis, C=1024), threshold = 16383-th smallest |x| over
//   the N=32768 leading entries; out = (|x| <= thr[c]) ? 0 : x.
//
// Round 8: same zero-atomic design as R7, but collect grid 256 -> 1024 blocks
// (32 rows each) to fix the 21%-occupancy latency limit ncu exposed.

#define C_DIM   1024
#define N_ROWS  32768
#define RANK0   16383            // int(0.5 * 32768) - 1
#define W_LO    0.64f
#define W_HI    0.71f
#define NBLK    1024             // collect blocks
#define RPB     (N_ROWS / NBLK)  // 32 rows per collect block
#define CAPB    16               // per column-block cap (lambda = 1.42, P(>16)~1e-13)
#define CAP     2048             // per-column total cap (mean 1457, sd 37)
#define SMALLC  288              // bin-mate capacity in select
#define BPT     (NBLK / 256)     // column-blocks handled per select thread = 4

// [col][blk][CAPB] : per-column contiguous -> coalesced select reads. 64 MB,
// only ~6 MB ever touched.
__device__ unsigned g_cand[(size_t)C_DIM * NBLK * CAPB];
// [blk][col] : warp-coalesced collect writes. 4 MB each.
__device__ int      g_cnt[NBLK * C_DIM];
__device__ int      g_below[NBLK * C_DIM];
__device__ __align__(16) float g_thr[C_DIM];

// -------------------------------------------------------------------------
// Pass 1: one full read of x. Thread t exclusively owns columns 4t..4t+3
// within its block -> counts and candidate slots need no synchronization.
// grid = 1024 blocks x 256 threads; each block covers 32 rows.
// -------------------------------------------------------------------------
__global__ void __launch_bounds__(256) k_collect(const float4* __restrict__ x) {
    const int t    = threadIdx.x;
    const int blk  = blockIdx.x;
    const int col0 = t * 4;
    const int row0 = blk * RPB;

    int b0 = 0, b1 = 0, b2 = 0, b3 = 0;   // below-window counts
    int n0 = 0, n1 = 0, n2 = 0, n3 = 0;   // in-window candidate counts

    unsigned* c0 = &g_cand[(size_t)(col0 + 0) * (NBLK * CAPB) + blk * CAPB];
    unsigned* c1 = c0 + (size_t)(NBLK * CAPB);
    unsigned* c2 = c1 + (size_t)(NBLK * CAPB);
    unsigned* c3 = c2 + (size_t)(NBLK * CAPB);

    #pragma unroll 8
    for (int j = 0; j < RPB; ++j) {
        float4 v = x[(size_t)(row0 + j) * 256 + t];
        float a;

        a = fabsf(v.x);
        if (a < W_LO) b0++;
        else if (a <= W_HI) { if (n0 < CAPB) c0[n0] = __float_as_uint(a); n0++; }

        a = fabsf(v.y);
        if (a < W_LO) b1++;
        else if (a <= W_HI) { if (n1 < CAPB) c1[n1] = __float_as_uint(a); n1++; }

        a = fabsf(v.z);
        if (a < W_LO) b2++;
        else if (a <= W_HI) { if (n2 < CAPB) c2[n2] = __float_as_uint(a); n2++; }

        a = fabsf(v.w);
        if (a < W_LO) b3++;
        else if (a <= W_HI) { if (n3 < CAPB) c3[n3] = __float_as_uint(a); n3++; }
    }

    const int base = blk * C_DIM + col0;   // [blk][col]: coalesced stores
    g_cnt[base + 0] = n0;    g_cnt[base + 1] = n1;
    g_cnt[base + 2] = n2;    g_cnt[base + 3] = n3;
    g_below[base + 0] = b0;  g_below[base + 1] = b1;
    g_below[base + 2] = b2;  g_below[base + 3] = b3;
}

// -------------------------------------------------------------------------
// Pass 2: one block per column. Each thread owns BPT=4 column-blocks: load
// their counts, scan, compact candidates into shared, then exact selection:
// all candidates share exponent 126 (window subset of [0.5,1)), so a 4096-bin
// histogram on mantissa bits [22:11] plus an exact resolve among bin-mates
// yields the exact k-th |x|. Fallback (rank outside window / any overflow):
// exact 4-pass byte-wise MSD radix select over the raw column.
// -------------------------------------------------------------------------
__global__ void __launch_bounds__(256) k_select(const float* __restrict__ x) {
    __shared__ unsigned sdata[CAP];     //  8 KB
    __shared__ int      hist[4096];     // 16 KB (fallback reuses first 256)
    __shared__ int      seg[256];       // per-thread candidate sums -> scan segs
    __shared__ int      bels[256];      // per-thread below sums
    __shared__ int      mxs[256];       // per-thread max cell count
    __shared__ int      offs[256];      // per-thread candidate base offset
    __shared__ unsigned ssmall[SMALLC];
    __shared__ int      s_smallcnt;
    __shared__ int      s_fb, s_n, s_r;
    __shared__ int      s_bin, s_r2;
    __shared__ unsigned s_prefix;
    __shared__ int      s_rank;

    const int c = blockIdx.x;
    const int t = threadIdx.x;

    int cb[BPT];
    int sum = 0, bel = 0, mx = 0;
    #pragma unroll
    for (int u = 0; u < BPT; ++u) {
        const int b = t * BPT + u;
        cb[u] = g_cnt[b * C_DIM + c];
        bel  += g_below[b * C_DIM + c];
        sum  += cb[u];
        if (cb[u] > mx) mx = cb[u];
    }
    seg[t] = sum;  bels[t] = bel;  mxs[t] = mx;
    __syncthreads();

    if (t == 0) {
        int tot = 0, m = 0, belt = 0;
        for (int i = 0; i < 256; ++i) {
            offs[i] = tot;
            tot  += seg[i];
            belt += bels[i];
            if (mxs[i] > m) m = mxs[i];
        }
        const int r = RANK0 - belt;
        s_n  = tot;
        s_r  = r;
        s_fb = (m > CAPB || tot > CAP || r < 0 || r >= tot) ? 1 : 0;
        s_smallcnt = 0;
    }
    __syncthreads();

    const int n = s_n;
    const int r = s_r;

    if (!s_fb) {
        // Compact: thread t copies its BPT block-segments (coalesced-ish L2 reads).
        {
            int o = offs[t];
            #pragma unroll
            for (int u = 0; u < BPT; ++u) {
                const int b = t * BPT + u;
                const unsigned* src = &g_cand[(size_t)c * (NBLK * CAPB) + b * CAPB];
                for (int j = 0; j < cb[u]; ++j) sdata[o + j] = src[j];
                o += cb[u];
            }
        }
        for (int i = t; i < 4096; i += 256) hist[i] = 0;
        __syncthreads();

        for (int i = t; i < n; i += 256)
            atomicAdd(&hist[(sdata[i] >> 11) & 0xFFF], 1);
        __syncthreads();

        // segmented prefix: 256 segments of 16 bins
        int s = 0;
        #pragma unroll
        for (int u = 0; u < 16; ++u) s += hist[t * 16 + u];
        seg[t] = s;
        __syncthreads();

        if (t == 0) {
            int cum = 0, si = 0;
            while (cum + seg[si] <= r) { cum += seg[si]; ++si; }
            int b = si * 16;
            while (cum + hist[b] <= r) { cum += hist[b]; ++b; }
            s_bin = b;
            s_r2  = r - cum;
        }
        __syncthreads();

        const unsigned bsel = (unsigned)s_bin;
        for (int i = t; i < n; i += 256) {
            if (((sdata[i] >> 11) & 0xFFF) == bsel) {
                int p = atomicAdd(&s_smallcnt, 1);
                if (p < SMALLC) ssmall[p] = sdata[i];
            }
        }
        __syncthreads();

        if (t == 0) {
            int m = s_smallcnt;
            if (m > SMALLC) {
                s_fb = 1;                      // pathological: redo exactly
            } else {
                const int r2 = s_r2;
                unsigned ans = 0;
                for (int i = 0; i < m; ++i) {
                    unsigned v = ssmall[i];
                    int less = 0, eq = 0;
                    for (int j = 0; j < m; ++j) {
                        less += (ssmall[j] < v);
                        eq   += (ssmall[j] == v);
                    }
                    if (less <= r2 && r2 < less + eq) { ans = v; break; }
                }
                g_thr[c] = __uint_as_float(ans);
            }
        }
        __syncthreads();
    }

    if (s_fb) {
        // Exact MSD radix select over the whole column (4 x 8-bit passes).
        if (t == 0) { s_prefix = 0; s_rank = RANK0; }
        for (int shift = 24; shift >= 0; shift -= 8) {
            hist[t] = 0;                       // only 256 bins used here
            __syncthreads();
            const unsigned pfx = s_prefix;
            const int hs = shift + 8;
            for (int row = t; row < N_ROWS; row += 256) {
                unsigned key = __float_as_uint(fabsf(x[(size_t)row * C_DIM + c]));
                bool ok = (hs >= 32) || ((key >> hs) == (pfx >> hs));
                if (ok) atomicAdd(&hist[(key >> shift) & 255], 1);
            }
            __syncthreads();
            if (t == 0) {
                int cum = 0, b = 0;
                while (cum + hist[b] <= s_rank) { cum += hist[b]; ++b; }
                s_rank  -= cum;
                s_prefix |= ((unsigned)b) << shift;
            }
            __syncthreads();
        }
        if (t == 0) g_thr[c] = __uint_as_float(s_prefix);
    }
}

// -------------------------------------------------------------------------
// Pass 3: streaming mask. blockDim must be 256 so each thread's column group
// (threadIdx.x) is loop-invariant -> threshold float4 hoisted out of the loop.
// -------------------------------------------------------------------------
__global__ void __launch_bounds__(256) k_mask(const float4* __restrict__ x,
                                              float4* __restrict__ out,
                                              int n4) {
    const float4 thr = reinterpret_cast<const float4*>(g_thr)[threadIdx.x];
    const int stride = gridDim.x * blockDim.x;   // multiple of 256
    for (int i = blockIdx.x * blockDim.x + threadIdx.x; i < n4; i += stride) {
        float4 v = x[i];
        float4 o;
        o.x = (fabsf(v.x) <= thr.x) ? 0.0f : v.x;
        o.y = (fabsf(v.y) <= thr.y) ? 0.0f : v.y;
        o.z = (fabsf(v.z) <= thr.z) ? 0.0f : v.z;
        o.w = (fabsf(v.w) <= thr.w) ? 0.0f : v.w;
        out[i] = o;
    }
}

extern "C" void kernel_launch(void* const* d_in, const int* in_sizes, int n_in,
                              void* d_out, int out_size) {
    const float* x = (const float*)d_in[0];
    float* out     = (float*)d_out;
    const int n4   = out_size / 4;               // 8,388,608 float4s

    k_collect<<<NBLK, 256>>>((const float4*)x);
    k_select <<<C_DIM, 256>>>(x);
    k_mask   <<<8192, 256>>>((const float4*)x, (float4*)out, n4);
}

// round 10
// speedup vs baseline: 2.0766x; 1.1205x over previous
#include <cuda_runtime.h>
#include <cuda_bf16.h>

// TargetedDropout inference path:
//   per channel c (last axis, C=1024), threshold = 16383-th smallest |x| over
//   the N=32768 leading entries; out = (|x| <= thr[c]) ? 0 : x.
//
// Round 9: collect gets explicit MLP=4 load batching + packed meta word;
// select gets a shfl-based parallel scan instead of the serial t==0 scan.
// Zero global atomics; exact in-window histogram select; always-correct
// per-column radix-select fallback.

#define C_DIM   1024
#define N_ROWS  32768
#define RANK0   16383            // int(0.5 * 32768) - 1
#define W_LO    0.64f
#define W_HI    0.71f
#define NBLK    1024             // collect blocks
#define RPB     (N_ROWS / NBLK)  // 32 rows per collect block
#define CAPB    16               // per column-block cap (lambda=1.42, P(>16)~1e-13)
#define CAP     2048             // per-column total cap (mean 1457, sd 37)
#define SMALLC  288              // bin-mate capacity in select
#define BPT     (NBLK / 256)     // column-blocks per select thread = 4

// [col][blk][CAPB] : per-column contiguous -> coalesced select reads.
__device__ unsigned g_cand[(size_t)C_DIM * NBLK * CAPB];
// [blk][col] packed meta: candidate_count | (below_count << 16). 4 MB.
__device__ int      g_meta[NBLK * C_DIM];
__device__ __align__(16) float g_thr[C_DIM];

// -------------------------------------------------------------------------
// Pass 1: one full read of x. Thread t exclusively owns columns 4t..4t+3
// within its block -> no synchronization. Loads batched 4-deep for MLP.
// grid = 1024 blocks x 256 threads; each block covers 32 rows.
// -------------------------------------------------------------------------
__global__ void __launch_bounds__(256) k_collect(const float4* __restrict__ x) {
    const int t    = threadIdx.x;
    const int blk  = blockIdx.x;
    const int col0 = t * 4;
    const int row0 = blk * RPB;

    int b0 = 0, b1 = 0, b2 = 0, b3 = 0;   // below-window counts
    int n0 = 0, n1 = 0, n2 = 0, n3 = 0;   // in-window candidate counts

    unsigned* c0 = &g_cand[(size_t)(col0 + 0) * (NBLK * CAPB) + blk * CAPB];
    unsigned* c1 = c0 + (size_t)(NBLK * CAPB);
    unsigned* c2 = c1 + (size_t)(NBLK * CAPB);
    unsigned* c3 = c2 + (size_t)(NBLK * CAPB);

#define PROC(v)                                                               \
    do {                                                                      \
        float a;                                                              \
        a = fabsf((v).x);                                                     \
        b0 += (a < W_LO);                                                     \
        if (a >= W_LO && a <= W_HI) {                                         \
            if (n0 < CAPB) c0[n0] = __float_as_uint(a);                       \
            n0++;                                                             \
        }                                                                     \
        a = fabsf((v).y);                                                     \
        b1 += (a < W_LO);                                                     \
        if (a >= W_LO && a <= W_HI) {                                         \
            if (n1 < CAPB) c1[n1] = __float_as_uint(a);                       \
            n1++;                                                             \
        }                                                                     \
        a = fabsf((v).z);                                                     \
        b2 += (a < W_LO);                                                     \
        if (a >= W_LO && a <= W_HI) {                                         \
            if (n2 < CAPB) c2[n2] = __float_as_uint(a);                       \
            n2++;                                                             \
        }                                                                     \
        a = fabsf((v).w);                                                     \
        b3 += (a < W_LO);                                                     \
        if (a >= W_LO && a <= W_HI) {                                         \
            if (n3 < CAPB) c3[n3] = __float_as_uint(a);                       \
            n3++;                                                             \
        }                                                                     \
    } while (0)

    #pragma unroll
    for (int j0 = 0; j0 < RPB; j0 += 4) {
        // Front-batched independent loads: MLP = 4.
        float4 v0 = x[(size_t)(row0 + j0 + 0) * 256 + t];
        float4 v1 = x[(size_t)(row0 + j0 + 1) * 256 + t];
        float4 v2 = x[(size_t)(row0 + j0 + 2) * 256 + t];
        float4 v3 = x[(size_t)(row0 + j0 + 3) * 256 + t];
        PROC(v0);
        PROC(v1);
        PROC(v2);
        PROC(v3);
    }
#undef PROC

    const int base = blk * C_DIM + col0;   // [blk][col]: coalesced stores
    g_meta[base + 0] = n0 | (b0 << 16);
    g_meta[base + 1] = n1 | (b1 << 16);
    g_meta[base + 2] = n2 | (b2 << 16);
    g_meta[base + 3] = n3 | (b3 << 16);
}

// -------------------------------------------------------------------------
// Pass 2: one block per column. Each thread owns BPT=4 column-blocks: load
// packed meta, shfl-scan the offsets, compact candidates into shared, then
// exact selection: all candidates share exponent 126 (window in [0.5,1)), so
// a 4096-bin histogram on mantissa bits [22:11] plus an exact resolve among
// bin-mates yields the exact k-th |x|. Fallback (rank outside window / any
// overflow): exact 4-pass byte-wise MSD radix select over the raw column.
// -------------------------------------------------------------------------
__global__ void __launch_bounds__(256) k_select(const float* __restrict__ x) {
    __shared__ unsigned sdata[CAP];     //  8 KB
    __shared__ int      hist[4096];     // 16 KB (fallback reuses first 256)
    __shared__ int      seg[256];       // per-thread sums for histogram scan
    __shared__ int      wsum[8];
    __shared__ unsigned ssmall[SMALLC];
    __shared__ int      s_smallcnt;
    __shared__ int      s_bel, s_mx;
    __shared__ int      s_fb, s_n, s_r;
    __shared__ int      s_bin, s_r2;
    __shared__ unsigned s_prefix;
    __shared__ int      s_rank;

    const int c    = blockIdx.x;
    const int t    = threadIdx.x;
    const int lane = t & 31;
    const int wid  = t >> 5;

    if (t == 0) { s_bel = 0; s_mx = 0; s_smallcnt = 0; }
    __syncthreads();

    int cb[BPT];
    int sum = 0, bel = 0, mx = 0;
    #pragma unroll
    for (int u = 0; u < BPT; ++u) {
        const int m = g_meta[(t * BPT + u) * C_DIM + c];
        cb[u] = m & 0xFFFF;
        bel  += m >> 16;
        sum  += cb[u];
        if (cb[u] > mx) mx = cb[u];
    }
    atomicAdd(&s_bel, bel);
    atomicMax(&s_mx, mx);

    // Exclusive prefix scan of per-thread sums (warp shfl + 8-wide base scan).
    int v = sum;
    #pragma unroll
    for (int d = 1; d < 32; d <<= 1) {
        int o = __shfl_up_sync(0xFFFFFFFFu, v, d);
        if (lane >= d) v += o;
    }
    if (lane == 31) wsum[wid] = v;
    __syncthreads();
    if (t == 0) {
        int acc = 0;
        #pragma unroll
        for (int i = 0; i < 8; ++i) { int tmp = wsum[i]; wsum[i] = acc; acc += tmp; }
        s_n = acc;
        const int r = RANK0 - s_bel;
        s_r = r;
        s_fb = (s_mx > CAPB || acc > CAP || r < 0 || r >= acc) ? 1 : 0;
    }
    __syncthreads();

    const int excl = wsum[wid] + v - sum;    // this thread's base offset
    const int n = s_n;
    const int r = s_r;

    if (!s_fb) {
        // Compact: thread t copies its BPT block-segments (L2-resident reads).
        {
            int o = excl;
            #pragma unroll
            for (int u = 0; u < BPT; ++u) {
                const unsigned* src =
                    &g_cand[(size_t)c * (NBLK * CAPB) + (t * BPT + u) * CAPB];
                for (int j = 0; j < cb[u]; ++j) sdata[o + j] = src[j];
                o += cb[u];
            }
        }
        for (int i = t; i < 4096; i += 256) hist[i] = 0;
        __syncthreads();

        for (int i = t; i < n; i += 256)
            atomicAdd(&hist[(sdata[i] >> 11) & 0xFFF], 1);
        __syncthreads();

        // segmented prefix: 256 segments of 16 bins
        int s = 0;
        #pragma unroll
        for (int u = 0; u < 16; ++u) s += hist[t * 16 + u];
        seg[t] = s;
        __syncthreads();

        if (t == 0) {
            int cum = 0, si = 0;
            while (cum + seg[si] <= r) { cum += seg[si]; ++si; }
            int b = si * 16;
            while (cum + hist[b] <= r) { cum += hist[b]; ++b; }
            s_bin = b;
            s_r2  = r - cum;
        }
        __syncthreads();

        const unsigned bsel = (unsigned)s_bin;
        for (int i = t; i < n; i += 256) {
            if (((sdata[i] >> 11) & 0xFFF) == bsel) {
                int p = atomicAdd(&s_smallcnt, 1);
                if (p < SMALLC) ssmall[p] = sdata[i];
            }
        }
        __syncthreads();

        if (t == 0) {
            int m = s_smallcnt;
            if (m > SMALLC) {
                s_fb = 1;                      // pathological: redo exactly
            } else {
                const int r2 = s_r2;
                unsigned ans = 0;
                for (int i = 0; i < m; ++i) {
                    unsigned vv = ssmall[i];
                    int less = 0, eq = 0;
                    for (int j = 0; j < m; ++j) {
                        less += (ssmall[j] < vv);
                        eq   += (ssmall[j] == vv);
                    }
                    if (less <= r2 && r2 < less + eq) { ans = vv; break; }
                }
                g_thr[c] = __uint_as_float(ans);
            }
        }
        __syncthreads();
    }

    if (s_fb) {
        // Exact MSD radix select over the whole column (4 x 8-bit passes).
        if (t == 0) { s_prefix = 0; s_rank = RANK0; }
        for (int shift = 24; shift >= 0; shift -= 8) {
            hist[t] = 0;                       // only 256 bins used here
            __syncthreads();
            const unsigned pfx = s_prefix;
            const int hs = shift + 8;
            for (int row = t; row < N_ROWS; row += 256) {
                unsigned key = __float_as_uint(fabsf(x[(size_t)row * C_DIM + c]));
                bool ok = (hs >= 32) || ((key >> hs) == (pfx >> hs));
                if (ok) atomicAdd(&hist[(key >> shift) & 255], 1);
            }
            __syncthreads();
            if (t == 0) {
                int cum = 0, b = 0;
                while (cum + hist[b] <= s_rank) { cum += hist[b]; ++b; }
                s_rank  -= cum;
                s_prefix |= ((unsigned)b) << shift;
            }
            __syncthreads();
        }
        if (t == 0) g_thr[c] = __uint_as_float(s_prefix);
    }
}

// -------------------------------------------------------------------------
// Pass 3: streaming mask. blockDim must be 256 so each thread's column group
// (threadIdx.x) is loop-invariant -> threshold float4 hoisted out of the loop.
// -------------------------------------------------------------------------
__global__ void __launch_bounds__(256) k_mask(const float4* __restrict__ x,
                                              float4* __restrict__ out,
                                              int n4) {
    const float4 thr = reinterpret_cast<const float4*>(g_thr)[threadIdx.x];
    const int stride = gridDim.x * blockDim.x;   // multiple of 256
    for (int i = blockIdx.x * blockDim.x + threadIdx.x; i < n4; i += stride) {
        float4 v = x[i];
        float4 o;
        o.x = (fabsf(v.x) <= thr.x) ? 0.0f : v.x;
        o.y = (fabsf(v.y) <= thr.y) ? 0.0f : v.y;
        o.z = (fabsf(v.z) <= thr.z) ? 0.0f : v.z;
        o.w = (fabsf(v.w) <= thr.w) ? 0.0f : v.w;
        out[i] = o;
    }
}

extern "C" void kernel_launch(void* const* d_in, const int* in_sizes, int n_in,
                              void* d_out, int out_size) {
    const float* x = (const float*)d_in[0];
    float* out     = (float*)d_out;
    const int n4   = out_size / 4;               // 8,388,608 float4s

    k_collect<<<NBLK, 256>>>((const float4*)x);
    k_select <<<C_DIM, 256>>>(x);
    k_mask   <<<8192, 256>>>((const float4*)x, (float4*)out, n4);
}